// round 4
// baseline (speedup 1.0000x reference)
#include <cuda_runtime.h>
#include <stdint.h>

// ---------------- problem constants ----------------
#define TSTEPS 512
#define BSZ    256
#define NIN    128
#define NHID   512
#define NOUT   10
#define DTc    0.042f
#define GAMc   2.7f
#define EPSc   4.7f

// ---------------- kernel config ----------------
#define NCTA    128          // 8 M-tiles(32) x 16 N-tiles(32)
#define THREADS 384          // 12 warps = wn(2: n16) x kh(6: 24 kb)
#define NKB     144
#define KH      6
#define JPW     24           // kb per kh group

// smem layout (words)
#define AS_WORDS  (NKB*256)               // 36864 : A panel [kb][r(32)][kk(8)]; W staging at init
#define PART_OFF  AS_WORDS
#define PART_STRIDE 36
#define PART_WORDS (KH*32*PART_STRIDE)    // 6912
#define BIAS_OFF  (PART_OFF + PART_WORDS)
#define SMEM_WORDS (BIAS_OFF + 32)
#define SMEM_BYTES (SMEM_WORDS*4)         // 175,232 B

// ---------------- device scratch ----------------
__device__ float    g_hy[2][BSZ*NHID];
__device__ float    g_hz[2][BSZ*NHID];
__device__ unsigned g_bar[(TSTEPS+1)*8];  // per (t, mi) group counters

// ---------------- helpers ----------------
__device__ __forceinline__ float fast_tanh(float v) {
    float e = __expf(2.0f * v);
    return 1.0f - __fdividef(2.0f, e + 1.0f);
}
__device__ __forceinline__ unsigned to_tf32(float f) {
    unsigned u;
    asm("cvt.rna.tf32.f32 %0, %1;" : "=r"(u) : "f"(f));
    return u;
}
__device__ __forceinline__ void mma_tf32(float* d,
                                         unsigned a0, unsigned a1, unsigned a2, unsigned a3,
                                         unsigned b0, unsigned b1) {
    asm volatile("mma.sync.aligned.m16n8k8.row.col.f32.tf32.tf32.f32 "
                 "{%0,%1,%2,%3}, {%4,%5,%6,%7}, {%8,%9}, {%0,%1,%2,%3};"
                 : "+f"(d[0]), "+f"(d[1]), "+f"(d[2]), "+f"(d[3])
                 : "r"(a0), "r"(a1), "r"(a2), "r"(a3), "r"(b0), "r"(b1));
}
__device__ __forceinline__ void bar_arrive(int idx) {
    asm volatile("red.release.gpu.global.add.u32 [%0], 1;" :: "l"(&g_bar[idx]) : "memory");
}
__device__ __forceinline__ void poll16(int idx) {
    unsigned v;
    do {
        asm volatile("ld.acquire.gpu.global.u32 %0, [%1];" : "=r"(v) : "l"(&g_bar[idx]) : "memory");
    } while (v < 16u);
}
#define COMMIT() asm volatile("cp.async.commit_group;")
#define WAITG0() asm volatile("cp.async.wait_group 0;")

// ---------------- single persistent kernel ----------------
__global__ void __launch_bounds__(THREADS, 1)
cornn_persist(const float* __restrict__ x, const float* __restrict__ W,
              const float* __restrict__ bias,
              const float* __restrict__ Wout, const float* __restrict__ bout,
              float* __restrict__ out) {
    extern __shared__ float smem[];
    float* As   = smem;
    float* Part = smem + PART_OFF;
    float* Bsh  = smem + BIAS_OFF;

    const int tid  = threadIdx.x;
    const int cta  = blockIdx.x;
    const int mi   = cta >> 4;            // 0..7
    const int ni   = cta & 15;            // 0..15
    const int lane = tid & 31;
    const int warp = tid >> 5;
    const int wn   = warp & 1;            // n16 half
    const int kh   = warp >> 1;           // 0..5 : k-slice, group of 2 warps
    const int gtid = tid & 63;            // id within kh group

    const unsigned asbase = (unsigned)__cvta_generic_to_shared(As);

    // ---- init: W slice -> smem (tf32-prerounded), frags -> regs ----
    for (int i = tid; i < AS_WORDS; i += THREADS) {
        int n  = i & 31;
        int kk = (i >> 5) & 7;
        int kb = i >> 8;
        As[kb * 256 + n * 8 + kk] =
            __uint_as_float(to_tf32(W[(size_t)(kb * 8 + kk) * NHID + ni * 32 + n]));
    }
    if (tid < 32) Bsh[tid] = bias[ni * 32 + tid];
    __syncthreads();

    unsigned wb0[JPW][2], wb1[JPW][2];
    {
        const int bfo = wn * 128 + (lane >> 2) * 8 + (lane & 3) * 2;
#pragma unroll
        for (int j = 0; j < JPW; ++j) {
            const float* bs = As + (kh * JPW + j) * 256 + bfo;
#pragma unroll
            for (int nf = 0; nf < 2; ++nf) {
                float2 v = *(const float2*)(bs + nf * 64);
                wb0[j][nf] = __float_as_uint(v.x);
                wb1[j][nf] = __float_as_uint(v.y);
            }
        }
    }
    __syncthreads();   // frags read before As is reused as A panel

    // ---- zero initial state (owners: tid<256, 4 elems each) ----
    const int srow = tid >> 3;            // 0..31 (tid<256)
    const int scol = (tid & 7) * 4;
    if (tid < 256) {
        size_t gi = (size_t)(mi * 32 + srow) * NHID + ni * 32 + scol;
        float4 z = make_float4(0.f, 0.f, 0.f, 0.f);
        *(float4*)&g_hz[0][gi] = z;
        *(float4*)&g_hy[0][gi] = z;
    }
    __syncthreads();
    if (tid == 0) bar_arrive(mi);         // gb(t=0, mi)

    // ---- per-thread staging constants: thread (r,q) does piece (kb,r,q) ----
    const int q    = gtid & 1;
    const int r    = (gtid >> 1) & 31;
    const int brow = mi * 32 + r;
    const unsigned dsm0 = asbase + (unsigned)((r * 8 + q * 4) << 2);  // + kb*1024

    // x prestage for t=0 (kh0 group only; kb 0..15 are pure x)
    if (kh == 0) {
#pragma unroll
        for (int kb = 0; kb < 16; ++kb) {
            const float* src = x + ((size_t)0 * BSZ + brow) * NIN + kb * 8 + q * 4;
            asm volatile("cp.async.cg.shared.global [%0], [%1], 16;"
                         :: "r"(dsm0 + kb * 1024u), "l"(src) : "memory");
        }
        COMMIT();
    }

    const int arow = (lane >> 2) * 8 + (lane & 3) * 2;
    float hyr[4] = {0, 0, 0, 0}, hzr[4] = {0, 0, 0, 0};

    for (int t = 0; t < TSTEPS; ++t) {
        const int rb = t & 1, wbuf = rb ^ 1;
        const float* hzc = g_hz[rb];
        const float* hyc = g_hy[rb];

        // wait for all 16 producers of rows mi at step t
        if (lane == 0) poll16(t * 8 + mi);
        __syncwarp();

        // stage own k-range (kh0 skips prestaged x part)
        {
            const int kbe = kh * JPW + JPW;
            for (int kb = (kh == 0 ? 16 : kh * JPW); kb < kbe; ++kb) {
                int kg = kb * 8 + q * 4;
                const float* src;
                if (kg < NIN)             src = x   + ((size_t)t * BSZ + brow) * NIN + kg;
                else if (kg < NIN + NHID) src = hzc + (size_t)brow * NHID + (kg - NIN);
                else                      src = hyc + (size_t)brow * NHID + (kg - NIN - NHID);
                asm volatile("cp.async.cg.shared.global [%0], [%1], 16;"
                             :: "r"(dsm0 + (unsigned)kb * 1024u), "l"(src) : "memory");
            }
        }
        COMMIT();
        WAITG0();
        asm volatile("bar.sync %0, %1;" :: "r"(1 + kh), "r"(64) : "memory");

        // ---- compute: m32 x n16, 24 k8-blocks ----
        float acc0[2][4], acc1[2][4];
#pragma unroll
        for (int nf = 0; nf < 2; ++nf)
#pragma unroll
            for (int c = 0; c < 4; ++c) { acc0[nf][c] = 0.f; acc1[nf][c] = 0.f; }

        const float* Abase = As + (kh * JPW) * 256 + arow;
#pragma unroll
        for (int j = 0; j < JPW; ++j) {
            const float* ab = Abase + j * 256;
            float2 p0 = *(const float2*)(ab);
            float2 p1 = *(const float2*)(ab + 64);
            float2 p2 = *(const float2*)(ab + 128);
            float2 p3 = *(const float2*)(ab + 192);
            unsigned a0 = to_tf32(p0.x), a2 = to_tf32(p0.y);
            unsigned a1 = to_tf32(p1.x), a3 = to_tf32(p1.y);
            unsigned a4 = to_tf32(p2.x), a6 = to_tf32(p2.y);
            unsigned a5 = to_tf32(p3.x), a7 = to_tf32(p3.y);
#pragma unroll
            for (int nf = 0; nf < 2; ++nf) {
                mma_tf32(acc0[nf], a0, a1, a2, a3, wb0[j][nf], wb1[j][nf]);
                mma_tf32(acc1[nf], a4, a5, a6, a7, wb0[j][nf], wb1[j][nf]);
            }
        }

        // ---- epilogue: partials -> smem, reduce 6, state update ----
        {
            float* P = Part + kh * (32 * PART_STRIDE);
            const int rr = lane >> 2;
            const int cc = (lane & 3) * 2;
#pragma unroll
            for (int nf = 0; nf < 2; ++nf) {
                int co = wn * 16 + nf * 8 + cc;
                *(float2*)(P + rr * PART_STRIDE + co)        = make_float2(acc0[nf][0], acc0[nf][1]);
                *(float2*)(P + (rr + 8) * PART_STRIDE + co)  = make_float2(acc0[nf][2], acc0[nf][3]);
                *(float2*)(P + (rr + 16) * PART_STRIDE + co) = make_float2(acc1[nf][0], acc1[nf][1]);
                *(float2*)(P + (rr + 24) * PART_STRIDE + co) = make_float2(acc1[nf][2], acc1[nf][3]);
            }
        }
        __syncthreads();
        if (tid < 256) {
            float4 s = make_float4(0.f, 0.f, 0.f, 0.f);
#pragma unroll
            for (int p = 0; p < KH; ++p) {
                float4 v = *(const float4*)(Part + p * (32 * PART_STRIDE) + srow * PART_STRIDE + scol);
                s.x += v.x; s.y += v.y; s.z += v.z; s.w += v.w;
            }
            float pre0 = fast_tanh(s.x + Bsh[scol]);
            float pre1 = fast_tanh(s.y + Bsh[scol + 1]);
            float pre2 = fast_tanh(s.z + Bsh[scol + 2]);
            float pre3 = fast_tanh(s.w + Bsh[scol + 3]);
            hzr[0] += DTc * (pre0 - GAMc * hyr[0] - EPSc * hzr[0]);  hyr[0] += DTc * hzr[0];
            hzr[1] += DTc * (pre1 - GAMc * hyr[1] - EPSc * hzr[1]);  hyr[1] += DTc * hzr[1];
            hzr[2] += DTc * (pre2 - GAMc * hyr[2] - EPSc * hzr[2]);  hyr[2] += DTc * hzr[2];
            hzr[3] += DTc * (pre3 - GAMc * hyr[3] - EPSc * hzr[3]);  hyr[3] += DTc * hzr[3];
            size_t gi = (size_t)(mi * 32 + srow) * NHID + ni * 32 + scol;
            __stcg((float4*)&g_hz[wbuf][gi], make_float4(hzr[0], hzr[1], hzr[2], hzr[3]));
            __stcg((float4*)&g_hy[wbuf][gi], make_float4(hyr[0], hyr[1], hyr[2], hyr[3]));
        }
        __syncthreads();
        if (tid == 0) bar_arrive((t + 1) * 8 + mi);

        // prestage x for next step (kh0 group; pure x region, state ptrs unused)
        if (kh == 0 && t + 1 < TSTEPS) {
#pragma unroll
            for (int kb = 0; kb < 16; ++kb) {
                const float* src = x + ((size_t)(t + 1) * BSZ + brow) * NIN + kb * 8 + q * 4;
                asm volatile("cp.async.cg.shared.global [%0], [%1], 16;"
                             :: "r"(dsm0 + kb * 1024u), "l"(src) : "memory");
            }
            COMMIT();
        }
    }

    // ---- final group barrier, counter self-reset, fused output GEMM ----
    if (lane == 0) poll16(TSTEPS * 8 + mi);
    __syncwarp();
    if (tid == 0) {
        unsigned old = atomicAdd(&g_bar[TSTEPS * 8 + mi], 1u);
        if (old == 31u) g_bar[TSTEPS * 8 + mi] = 0u;   // last passer resets
        for (int tt = ni; tt < TSTEPS; tt += 16) g_bar[tt * 8 + mi] = 0u;
    }

    // out = hy_final @ Wout + bout ; final hy in buffer 0 (t=511 wrote wbuf=0)
    if (warp < 2) {
        int row = cta * 2 + warp;                 // row's mi == this CTA's mi
        const float* h = g_hy[0] + (size_t)row * NHID;
        float acc[NOUT];
#pragma unroll
        for (int o = 0; o < NOUT; ++o) acc[o] = 0.f;
        for (int k = lane; k < NHID; k += 32) {
            float hv = __ldcg(h + k);
#pragma unroll
            for (int o = 0; o < NOUT; ++o) acc[o] += hv * Wout[k * NOUT + o];
        }
#pragma unroll
        for (int o = 0; o < NOUT; ++o) {
#pragma unroll
            for (int s = 16; s > 0; s >>= 1)
                acc[o] += __shfl_xor_sync(0xffffffffu, acc[o], s);
        }
        if (lane == 0) {
#pragma unroll
            for (int o = 0; o < NOUT; ++o) out[row * NOUT + o] = acc[o] + bout[o];
        }
    }
}

// ---------------- launch ----------------
extern "C" void kernel_launch(void* const* d_in, const int* in_sizes, int n_in,
                              void* d_out, int out_size) {
    (void)in_sizes; (void)n_in; (void)out_size;
    const float* x    = (const float*)d_in[0];
    const float* W    = (const float*)d_in[1];
    const float* b    = (const float*)d_in[2];
    const float* Wout = (const float*)d_in[3];
    const float* bout = (const float*)d_in[4];
    float* out = (float*)d_out;

    cudaFuncSetAttribute(cornn_persist, cudaFuncAttributeMaxDynamicSharedMemorySize, SMEM_BYTES);
    cornn_persist<<<NCTA, THREADS, SMEM_BYTES>>>(x, W, b, Wout, bout, out);
}

// round 5
// speedup vs baseline: 1.2035x; 1.2035x over previous
#include <cuda_runtime.h>
#include <cuda_fp16.h>
#include <stdint.h>

// ---------------- problem constants ----------------
#define TSTEPS 512
#define BSZ    256
#define NIN    128
#define NHID   512
#define NOUT   10
#define DTc    0.042f
#define GAMc   2.7f
#define EPSc   4.7f

// ---------------- kernel config ----------------
#define NCTA    128          // 8 M-tiles(32) x 16 N-tiles(32)
#define THREADS 288          // 9 warps, each = full m32 x n32, unique k-slice of 128
#define NWARP   9
#define JPW     8            // k16-blocks per warp
#define PS      34           // partial-tile row stride (words)

__device__ float    g_hy[2][BSZ*NHID];
__device__ float    g_hz[2][BSZ*NHID];
__device__ unsigned g_bar[(TSTEPS+1)*8];

// ---------------- helpers ----------------
__device__ __forceinline__ float fast_tanh(float v) {
    float e = __expf(2.0f * v);
    return 1.0f - __fdividef(2.0f, e + 1.0f);
}
__device__ __forceinline__ unsigned pack_h2(float lo, float hi) {
    __half2 h = __floats2half2_rn(lo, hi);
    return *reinterpret_cast<unsigned*>(&h);
}
__device__ __forceinline__ void mma_f16(float* d,
                                        unsigned a0, unsigned a1, unsigned a2, unsigned a3,
                                        unsigned b0, unsigned b1) {
    asm volatile("mma.sync.aligned.m16n8k16.row.col.f32.f16.f16.f32 "
                 "{%0,%1,%2,%3}, {%4,%5,%6,%7}, {%8,%9}, {%0,%1,%2,%3};"
                 : "+f"(d[0]), "+f"(d[1]), "+f"(d[2]), "+f"(d[3])
                 : "r"(a0), "r"(a1), "r"(a2), "r"(a3), "r"(b0), "r"(b1));
}
__device__ __forceinline__ void bar_arrive(int idx) {
    asm volatile("red.release.gpu.global.add.u32 [%0], 1;" :: "l"(&g_bar[idx]) : "memory");
}
__device__ __forceinline__ void poll16(int idx) {
    unsigned v;
    do {
        asm volatile("ld.acquire.gpu.global.u32 %0, [%1];" : "=r"(v) : "l"(&g_bar[idx]) : "memory");
    } while (v < 16u);
}
__device__ __forceinline__ float2 ldcg2(const float* p) {
    return __ldcg(reinterpret_cast<const float2*>(p));
}

// compute m32 x n32 partial over 8 k16-blocks, A straight from global (L2)
__device__ __forceinline__ void compute_tile(const float* rp0, const float* rp1,
                                             const float* rp2, const float* rp3,
                                             const unsigned wb0[JPW][4],
                                             const unsigned wb1[JPW][4],
                                             float acc0[4][4], float acc1[4][4]) {
#pragma unroll
    for (int j = 0; j < JPW; ++j) {
        float2 v0l = ldcg2(rp0 + j * 16);
        float2 v0h = ldcg2(rp0 + j * 16 + 8);
        float2 v1l = ldcg2(rp1 + j * 16);
        float2 v1h = ldcg2(rp1 + j * 16 + 8);
        float2 v2l = ldcg2(rp2 + j * 16);
        float2 v2h = ldcg2(rp2 + j * 16 + 8);
        float2 v3l = ldcg2(rp3 + j * 16);
        float2 v3h = ldcg2(rp3 + j * 16 + 8);
        unsigned a0l = pack_h2(v0l.x, v0l.y), a0h = pack_h2(v0h.x, v0h.y);
        unsigned a1l = pack_h2(v1l.x, v1l.y), a1h = pack_h2(v1h.x, v1h.y);
        unsigned a2l = pack_h2(v2l.x, v2l.y), a2h = pack_h2(v2h.x, v2h.y);
        unsigned a3l = pack_h2(v3l.x, v3l.y), a3h = pack_h2(v3h.x, v3h.y);
#pragma unroll
        for (int nf = 0; nf < 4; ++nf) {
            mma_f16(acc0[nf], a0l, a1l, a0h, a1h, wb0[j][nf], wb1[j][nf]);
            mma_f16(acc1[nf], a2l, a3l, a2h, a3h, wb0[j][nf], wb1[j][nf]);
        }
    }
}

// ---------------- single persistent kernel ----------------
__global__ void __launch_bounds__(THREADS, 1)
cornn_persist(const float* __restrict__ x, const float* __restrict__ W,
              const float* __restrict__ bias,
              const float* __restrict__ Wout, const float* __restrict__ bout,
              float* __restrict__ out) {
    __shared__ float Part[NWARP * 32 * PS];

    const int tid  = threadIdx.x;
    const int cta  = blockIdx.x;
    const int mi   = cta >> 4;            // 0..7
    const int ni   = cta & 15;            // 0..15
    const int lane = tid & 31;
    const int warp = tid >> 5;            // 0..8 : k-slice [128*warp, 128*warp+128)

    // ---- one-time: B fragments from W (global, read-only), fp16-packed ----
    // warp w, block j, nf: b0 = {W[k][n], W[k+1][n]}, b1 = {W[k+8][n], W[k+9][n]}
    unsigned wb0[JPW][4], wb1[JPW][4];
    {
        const int n = ni * 32 + (lane >> 2);   // + nf*8
#pragma unroll
        for (int j = 0; j < JPW; ++j) {
            const int k0 = warp * 128 + j * 16 + 2 * (lane & 3);
#pragma unroll
            for (int nf = 0; nf < 4; ++nf) {
                const float* wp = W + (size_t)k0 * NHID + n + nf * 8;
                wb0[j][nf] = pack_h2(wp[0],        wp[NHID]);
                wb1[j][nf] = pack_h2(wp[8 * NHID], wp[9 * NHID]);
            }
        }
    }
    // bias init values (nonzero only for warp 0 — it folds bias into its partial)
    float bc[4][2];
#pragma unroll
    for (int nf = 0; nf < 4; ++nf) {
        if (warp == 0) {
            int col = ni * 32 + nf * 8 + 2 * (lane & 3);
            bc[nf][0] = bias[col];
            bc[nf][1] = bias[col + 1];
        } else {
            bc[nf][0] = 0.f; bc[nf][1] = 0.f;
        }
    }

    // ---- zero initial state patch (buffer 0) ----
    const int srow = (tid & 255) >> 3;
    const int scol = (tid & 7) * 4;
    if (tid < 256) {
        size_t gi = (size_t)(mi * 32 + srow) * NHID + ni * 32 + scol;
        float4 z = make_float4(0.f, 0.f, 0.f, 0.f);
        __stcg((float4*)&g_hz[0][gi], z);
        __stcg((float4*)&g_hy[0][gi], z);
    }
    __syncthreads();
    if (tid == 0) bar_arrive(mi);          // arrive (t=0, mi)

    // per-thread A row offsets (4 row-groups of the m32 tile)
    const int arow = mi * 32 + (lane >> 2);
    const int akc  = 2 * (lane & 3);

    float hyr[4] = {0, 0, 0, 0}, hzr[4] = {0, 0, 0, 0};

    for (int t = 0; t < TSTEPS; ++t) {
        const int rb = t & 1, wbuf = rb ^ 1;
        const float* hzc = g_hz[rb];
        const float* hyc = g_hy[rb];

        float acc0[4][4], acc1[4][4];
#pragma unroll
        for (int nf = 0; nf < 4; ++nf) {
            acc0[nf][0] = bc[nf][0]; acc0[nf][1] = bc[nf][1];
            acc0[nf][2] = bc[nf][0]; acc0[nf][3] = bc[nf][1];
            acc1[nf][0] = bc[nf][0]; acc1[nf][1] = bc[nf][1];
            acc1[nf][2] = bc[nf][0]; acc1[nf][3] = bc[nf][1];
        }

        // warp 0: pure-x slice -> compute its partial BEFORE the barrier (hidden in wait)
        if (warp == 0) {
            const float* rx = x + ((size_t)t * BSZ + arow) * NIN + akc;
            compute_tile(rx, rx + 8 * NIN, rx + 16 * NIN, rx + 24 * NIN,
                         wb0, wb1, acc0, acc1);
            float* P = Part;   // slot 0 (free: previous reduce finished before this step)
            const int rr = lane >> 2, cc = 2 * (lane & 3);
#pragma unroll
            for (int nf = 0; nf < 4; ++nf) {
                int co = nf * 8 + cc;
                *(float2*)(P + rr * PS + co)        = make_float2(acc0[nf][0], acc0[nf][1]);
                *(float2*)(P + (rr + 8) * PS + co)  = make_float2(acc0[nf][2], acc0[nf][3]);
                *(float2*)(P + (rr + 16) * PS + co) = make_float2(acc1[nf][0], acc1[nf][1]);
                *(float2*)(P + (rr + 24) * PS + co) = make_float2(acc1[nf][2], acc1[nf][3]);
            }
        }
        // single poller, concurrent with warp 0's compute
        if (tid == 256) poll16(t * 8 + mi);
        __syncthreads();   // S1: state visible to all; Part[0] written

        if (warp != 0) {
            // k-slice region: warps 1-4 -> hz (k-128), warps 5-8 -> hy (k-640)
            const float* base = (warp <= 4) ? hzc : hyc;
            const int cb = warp * 128 - ((warp <= 4) ? 128 : 640);
            const float* rp = base + (size_t)arow * NHID + cb + akc;
            compute_tile(rp, rp + 8 * NHID, rp + 16 * NHID, rp + 24 * NHID,
                         wb0, wb1, acc0, acc1);
            float* P = Part + warp * (32 * PS);
            const int rr = lane >> 2, cc = 2 * (lane & 3);
#pragma unroll
            for (int nf = 0; nf < 4; ++nf) {
                int co = nf * 8 + cc;
                *(float2*)(P + rr * PS + co)        = make_float2(acc0[nf][0], acc0[nf][1]);
                *(float2*)(P + (rr + 8) * PS + co)  = make_float2(acc0[nf][2], acc0[nf][3]);
                *(float2*)(P + (rr + 16) * PS + co) = make_float2(acc1[nf][0], acc1[nf][1]);
                *(float2*)(P + (rr + 24) * PS + co) = make_float2(acc1[nf][2], acc1[nf][3]);
            }
        }
        __syncthreads();   // S2a: all partials written

        if (tid < 256) {
            float s0 = 0.f, s1 = 0.f, s2 = 0.f, s3 = 0.f;
#pragma unroll
            for (int p = 0; p < NWARP; ++p) {
                const float* q = Part + p * (32 * PS) + srow * PS + scol;
                s0 += q[0]; s1 += q[1]; s2 += q[2]; s3 += q[3];
            }
            float pre0 = fast_tanh(s0);
            float pre1 = fast_tanh(s1);
            float pre2 = fast_tanh(s2);
            float pre3 = fast_tanh(s3);
            hzr[0] += DTc * (pre0 - GAMc * hyr[0] - EPSc * hzr[0]);  hyr[0] += DTc * hzr[0];
            hzr[1] += DTc * (pre1 - GAMc * hyr[1] - EPSc * hzr[1]);  hyr[1] += DTc * hzr[1];
            hzr[2] += DTc * (pre2 - GAMc * hyr[2] - EPSc * hzr[2]);  hyr[2] += DTc * hzr[2];
            hzr[3] += DTc * (pre3 - GAMc * hyr[3] - EPSc * hzr[3]);  hyr[3] += DTc * hzr[3];
            size_t gi = (size_t)(mi * 32 + srow) * NHID + ni * 32 + scol;
            __stcg((float4*)&g_hz[wbuf][gi], make_float4(hzr[0], hzr[1], hzr[2], hzr[3]));
            __stcg((float4*)&g_hy[wbuf][gi], make_float4(hyr[0], hyr[1], hyr[2], hyr[3]));
        }
        __syncthreads();   // S2: state stores done CTA-wide
        if (tid == 0) bar_arrive((t + 1) * 8 + mi);
    }

    // ---- final group barrier, counter self-reset ----
    if (tid == 256) poll16(TSTEPS * 8 + mi);
    __syncthreads();
    if (tid == 0) {
        unsigned old = atomicAdd(&g_bar[TSTEPS * 8 + mi], 1u);
        if (old == 31u) g_bar[TSTEPS * 8 + mi] = 0u;   // last passer resets final
        for (int tt = ni; tt < TSTEPS; tt += 16) g_bar[tt * 8 + mi] = 0u;
    }

    // ---- fused output GEMM: out = hy_final @ Wout + bout (final hy in buffer 0) ----
    if (warp < 2) {
        int row = cta * 2 + warp;                 // row's mi == this CTA's mi
        const float* h = g_hy[0] + (size_t)row * NHID;
        float acc[NOUT];
#pragma unroll
        for (int o = 0; o < NOUT; ++o) acc[o] = 0.f;
        for (int k = lane; k < NHID; k += 32) {
            float hv = __ldcg(h + k);
#pragma unroll
            for (int o = 0; o < NOUT; ++o) acc[o] += hv * Wout[k * NOUT + o];
        }
#pragma unroll
        for (int o = 0; o < NOUT; ++o) {
#pragma unroll
            for (int s = 16; s > 0; s >>= 1)
                acc[o] += __shfl_xor_sync(0xffffffffu, acc[o], s);
        }
        if (lane == 0) {
#pragma unroll
            for (int o = 0; o < NOUT; ++o) out[row * NOUT + o] = acc[o] + bout[o];
        }
    }
}

// ---------------- launch ----------------
extern "C" void kernel_launch(void* const* d_in, const int* in_sizes, int n_in,
                              void* d_out, int out_size) {
    (void)in_sizes; (void)n_in; (void)out_size;
    const float* x    = (const float*)d_in[0];
    const float* W    = (const float*)d_in[1];
    const float* b    = (const float*)d_in[2];
    const float* Wout = (const float*)d_in[3];
    const float* bout = (const float*)d_in[4];
    float* out = (float*)d_out;

    cornn_persist<<<NCTA, THREADS>>>(x, W, b, Wout, bout, out);
}

// round 6
// speedup vs baseline: 1.8247x; 1.5161x over previous
#include <cuda_runtime.h>
#include <cuda_fp16.h>
#include <stdint.h>

// ---------------- problem constants ----------------
#define TSTEPS 512
#define BSZ    256
#define NIN    128
#define NHID   512
#define NOUT   10
#define DTc    0.042f
#define GAMc   2.7f
#define EPSc   4.7f

// ---------------- kernel config ----------------
#define NCTA    128          // 8 M-tiles(32) x 16 N-tiles(32)
#define KW      8            // warps; each = m32 x n32, k-slice of 128 (state only)
#define THREADS (KW*32)      // 256
#define JPW     8            // k16-blocks per warp
#define PS      36           // partial-tile row stride (16B-aligned rows)

// ---------------- device scratch ----------------
// fp16 state, permuted layout: row-major [256 rows][32 blocks of 16 cols];
// within a block, col-pair p (cols 2p,2p+1) stored at u32 position perm(p):
//   perm(p) = p<4 ? 2p : 2(p-4)+1   -> consumer lane c LDG.64 reads pairs {c, 4+c}
__device__ unsigned g_Hz[2][BSZ*256];
__device__ unsigned g_Hy[2][BSZ*256];
__device__ float    g_preX[(size_t)NCTA*TSTEPS*32*32];  // x@Wx + bias, per-CTA patches
__device__ float    g_hyf[BSZ*NHID];                    // final hy (fp32)
__device__ unsigned g_bar[(TSTEPS+1)*8];

// ---------------- helpers ----------------
__device__ __forceinline__ float fast_tanh(float v) {
    float e = __expf(2.0f * v);
    return 1.0f - __fdividef(2.0f, e + 1.0f);
}
__device__ __forceinline__ unsigned pack_h2(float lo, float hi) {
    __half2 h = __floats2half2_rn(lo, hi);
    return *reinterpret_cast<unsigned*>(&h);
}
__device__ __forceinline__ void mma_f16(float* d,
                                        unsigned a0, unsigned a1, unsigned a2, unsigned a3,
                                        unsigned b0, unsigned b1) {
    asm volatile("mma.sync.aligned.m16n8k16.row.col.f32.f16.f16.f32 "
                 "{%0,%1,%2,%3}, {%4,%5,%6,%7}, {%8,%9}, {%0,%1,%2,%3};"
                 : "+f"(d[0]), "+f"(d[1]), "+f"(d[2]), "+f"(d[3])
                 : "r"(a0), "r"(a1), "r"(a2), "r"(a3), "r"(b0), "r"(b1));
}
__device__ __forceinline__ void bar_arrive(int idx) {
    asm volatile("red.release.gpu.global.add.u32 [%0], 1;" :: "l"(&g_bar[idx]) : "memory");
}
__device__ __forceinline__ void poll16(int idx) {
    unsigned v;
    do {
        asm volatile("ld.acquire.gpu.global.u32 %0, [%1];" : "=r"(v) : "l"(&g_bar[idx]) : "memory");
    } while (v < 16u);
}
__device__ __forceinline__ float2 ldcg2(const float* p) {
    return __ldcg(reinterpret_cast<const float2*>(p));
}

// fp32-A compute tile (phase 1 only): m32 x n32 over 8 k16-blocks
__device__ __forceinline__ void compute_tile_f32(const float* rp0, const float* rp1,
                                                 const float* rp2, const float* rp3,
                                                 const unsigned b0[JPW][4],
                                                 const unsigned b1[JPW][4],
                                                 float acc0[4][4], float acc1[4][4]) {
#pragma unroll
    for (int j = 0; j < JPW; ++j) {
        float2 v0l = ldcg2(rp0 + j * 16), v0h = ldcg2(rp0 + j * 16 + 8);
        float2 v1l = ldcg2(rp1 + j * 16), v1h = ldcg2(rp1 + j * 16 + 8);
        float2 v2l = ldcg2(rp2 + j * 16), v2h = ldcg2(rp2 + j * 16 + 8);
        float2 v3l = ldcg2(rp3 + j * 16), v3h = ldcg2(rp3 + j * 16 + 8);
        unsigned a0l = pack_h2(v0l.x, v0l.y), a0h = pack_h2(v0h.x, v0h.y);
        unsigned a1l = pack_h2(v1l.x, v1l.y), a1h = pack_h2(v1h.x, v1h.y);
        unsigned a2l = pack_h2(v2l.x, v2l.y), a2h = pack_h2(v2h.x, v2h.y);
        unsigned a3l = pack_h2(v3l.x, v3l.y), a3h = pack_h2(v3h.x, v3h.y);
#pragma unroll
        for (int nf = 0; nf < 4; ++nf) {
            mma_f16(acc0[nf], a0l, a1l, a0h, a1h, b0[j][nf], b1[j][nf]);
            mma_f16(acc1[nf], a2l, a3l, a2h, a3h, b0[j][nf], b1[j][nf]);
        }
    }
}

// ---------------- single persistent kernel ----------------
__global__ void __launch_bounds__(THREADS, 1)
cornn_persist(const float* __restrict__ x, const float* __restrict__ W,
              const float* __restrict__ bias,
              const float* __restrict__ Wout, const float* __restrict__ bout,
              float* __restrict__ out) {
    __shared__ float Part[KW * 32 * PS];

    const int tid  = threadIdx.x;
    const int cta  = blockIdx.x;
    const int mi   = cta >> 4;            // 0..7
    const int ni   = cta & 15;            // 0..15
    const int lane = tid & 31;
    const int warp = tid >> 5;            // 0..7

    const int arow = mi * 32 + (lane >> 2);
    const int akc  = 2 * (lane & 3);
    const int rr   = lane >> 2;
    const int cc   = 2 * (lane & 3);

    // ================= phase 1: preX[t] = x_t @ W[0:128] + b (per-CTA patches) =================
    {
        unsigned xb0[JPW][4], xb1[JPW][4];
        const int n = ni * 32 + (lane >> 2);
#pragma unroll
        for (int j = 0; j < JPW; ++j) {
            const int k0 = j * 16 + 2 * (lane & 3);
#pragma unroll
            for (int nf = 0; nf < 4; ++nf) {
                const float* wp = W + (size_t)k0 * NHID + n + nf * 8;
                xb0[j][nf] = pack_h2(wp[0],        wp[NHID]);
                xb1[j][nf] = pack_h2(wp[8 * NHID], wp[9 * NHID]);
            }
        }
        float bc[4][2];
#pragma unroll
        for (int nf = 0; nf < 4; ++nf) {
            int col = ni * 32 + nf * 8 + cc;
            bc[nf][0] = bias[col];
            bc[nf][1] = bias[col + 1];
        }
        for (int i = 0; i < TSTEPS / KW; ++i) {
            const int t = warp + KW * i;
            float acc0[4][4], acc1[4][4];
#pragma unroll
            for (int nf = 0; nf < 4; ++nf) {
                acc0[nf][0] = bc[nf][0]; acc0[nf][1] = bc[nf][1];
                acc0[nf][2] = bc[nf][0]; acc0[nf][3] = bc[nf][1];
                acc1[nf][0] = bc[nf][0]; acc1[nf][1] = bc[nf][1];
                acc1[nf][2] = bc[nf][0]; acc1[nf][3] = bc[nf][1];
            }
            const float* rx = x + ((size_t)t * BSZ + arow) * NIN + akc;
            compute_tile_f32(rx, rx + 8 * NIN, rx + 16 * NIN, rx + 24 * NIN,
                             xb0, xb1, acc0, acc1);
            float* dst = g_preX + ((size_t)(cta * TSTEPS + t) * 32) * 32;
#pragma unroll
            for (int nf = 0; nf < 4; ++nf) {
                int co = nf * 8 + cc;
                __stcg((float2*)(dst + rr * 32 + co),        make_float2(acc0[nf][0], acc0[nf][1]));
                __stcg((float2*)(dst + (rr + 8) * 32 + co),  make_float2(acc0[nf][2], acc0[nf][3]));
                __stcg((float2*)(dst + (rr + 16) * 32 + co), make_float2(acc1[nf][0], acc1[nf][1]));
                __stcg((float2*)(dst + (rr + 24) * 32 + co), make_float2(acc1[nf][2], acc1[nf][3]));
            }
        }
    }

    // ================= init: zero fp16 state (buffer 0) + per-thread store slots =================
    const int srow = tid >> 3;                 // 0..31
    const int scol = (tid & 7) * 4;            // 0..28
    const int grow = mi * 32 + srow;
    const int gcol = ni * 32 + scol;
    const int blk  = gcol >> 4;
    const int pp   = (gcol & 15) >> 1;         // 0,2,4,6
    const int pos0 = (pp < 4) ? 2 * pp : 2 * pp - 7;
    const int pos1 = ((pp + 1) < 4) ? 2 * (pp + 1) : 2 * (pp + 1) - 7;
    const int hbase = grow * 256 + blk * 8;

    g_Hz[0][hbase + pos0] = 0u;  g_Hz[0][hbase + pos1] = 0u;
    g_Hy[0][hbase + pos0] = 0u;  g_Hy[0][hbase + pos1] = 0u;
    __syncthreads();
    if (tid == 0) bar_arrive(mi);

    // ================= main-loop B fragments: W rows 128 + warp*128 .. +128 =================
    unsigned wb0[JPW][4], wb1[JPW][4];
    {
        const int n = ni * 32 + (lane >> 2);
#pragma unroll
        for (int j = 0; j < JPW; ++j) {
            const int k0 = 128 + warp * 128 + j * 16 + 2 * (lane & 3);
#pragma unroll
            for (int nf = 0; nf < 4; ++nf) {
                const float* wp = W + (size_t)k0 * NHID + n + nf * 8;
                wb0[j][nf] = pack_h2(wp[0],        wp[NHID]);
                wb1[j][nf] = pack_h2(wp[8 * NHID], wp[9 * NHID]);
            }
        }
    }

    // consumer addressing: warp<4 -> hz, warp>=4 -> hy; block base within array
    const int grow0 = mi * 32 + (lane >> 2);
    const int bb0   = (warp & 3) * 8;
    const int hoff  = grow0 * 256 + bb0 * 8 + 2 * (lane & 3);

    float hyr[4] = {0, 0, 0, 0}, hzr[4] = {0, 0, 0, 0};

    // ================= recurrence =================
    for (int t = 0; t < TSTEPS; ++t) {
        const int rb = t & 1, wbuf = rb ^ 1;

        // prefetch CTA-private preX patch (available immediately; hides DRAM latency)
        float4 px = __ldcg((const float4*)(g_preX +
                         (((size_t)(cta * TSTEPS + t) * 32 + srow) * 32 + scol)));

        // per-warp poll: no CTA-wide sync between wait and compute
        if (lane == 0) poll16(t * 8 + mi);
        __syncwarp();

        const unsigned* hp = ((warp < 4) ? g_Hz[rb] : g_Hy[rb]) + hoff;

        float acc0[4][4], acc1[4][4];
#pragma unroll
        for (int nf = 0; nf < 4; ++nf)
#pragma unroll
            for (int c = 0; c < 4; ++c) { acc0[nf][c] = 0.f; acc1[nf][c] = 0.f; }

#pragma unroll
        for (int j = 0; j < JPW; ++j) {
            const unsigned* q = hp + j * 8;
            uint2 u0 = __ldcg((const uint2*)(q));
            uint2 u1 = __ldcg((const uint2*)(q + 8 * 256));
            uint2 u2 = __ldcg((const uint2*)(q + 16 * 256));
            uint2 u3 = __ldcg((const uint2*)(q + 24 * 256));
#pragma unroll
            for (int nf = 0; nf < 4; ++nf) {
                mma_f16(acc0[nf], u0.x, u1.x, u0.y, u1.y, wb0[j][nf], wb1[j][nf]);
                mma_f16(acc1[nf], u2.x, u3.x, u2.y, u3.y, wb0[j][nf], wb1[j][nf]);
            }
        }

        // write this warp's partial
        {
            float* P = Part + warp * (32 * PS);
#pragma unroll
            for (int nf = 0; nf < 4; ++nf) {
                int co = nf * 8 + cc;
                *(float2*)(P + rr * PS + co)        = make_float2(acc0[nf][0], acc0[nf][1]);
                *(float2*)(P + (rr + 8) * PS + co)  = make_float2(acc0[nf][2], acc0[nf][3]);
                *(float2*)(P + (rr + 16) * PS + co) = make_float2(acc1[nf][0], acc1[nf][1]);
                *(float2*)(P + (rr + 24) * PS + co) = make_float2(acc1[nf][2], acc1[nf][3]);
            }
        }
        __syncthreads();   // all partials in smem

        // reduce 8 partials + preX, tanh, state update, publish fp16 state
        {
            float s0 = px.x, s1 = px.y, s2 = px.z, s3 = px.w;
#pragma unroll
            for (int p = 0; p < KW; ++p) {
                const float* q = Part + p * (32 * PS) + srow * PS + scol;
                float4 v = *(const float4*)q;
                s0 += v.x; s1 += v.y; s2 += v.z; s3 += v.w;
            }
            float pre0 = fast_tanh(s0);
            float pre1 = fast_tanh(s1);
            float pre2 = fast_tanh(s2);
            float pre3 = fast_tanh(s3);
            hzr[0] += DTc * (pre0 - GAMc * hyr[0] - EPSc * hzr[0]);  hyr[0] += DTc * hzr[0];
            hzr[1] += DTc * (pre1 - GAMc * hyr[1] - EPSc * hzr[1]);  hyr[1] += DTc * hzr[1];
            hzr[2] += DTc * (pre2 - GAMc * hyr[2] - EPSc * hzr[2]);  hyr[2] += DTc * hzr[2];
            hzr[3] += DTc * (pre3 - GAMc * hyr[3] - EPSc * hzr[3]);  hyr[3] += DTc * hzr[3];

            unsigned* Hz = g_Hz[wbuf];
            unsigned* Hy = g_Hy[wbuf];
            __stcg(&Hz[hbase + pos0], pack_h2(hzr[0], hzr[1]));
            __stcg(&Hz[hbase + pos1], pack_h2(hzr[2], hzr[3]));
            __stcg(&Hy[hbase + pos0], pack_h2(hyr[0], hyr[1]));
            __stcg(&Hy[hbase + pos1], pack_h2(hyr[2], hyr[3]));
            if (t == TSTEPS - 1) {
                __stcg((float4*)&g_hyf[(size_t)grow * NHID + gcol],
                       make_float4(hyr[0], hyr[1], hyr[2], hyr[3]));
            }
        }
        __syncthreads();   // state stores done CTA-wide; Part safe to reuse
        if (tid == 0) bar_arrive((t + 1) * 8 + mi);
    }

    // ================= final barrier, counter self-reset, fused output GEMM =================
    if (tid == 0) poll16(TSTEPS * 8 + mi);
    __syncthreads();
    if (tid == 0) {
        unsigned old = atomicAdd(&g_bar[TSTEPS * 8 + mi], 1u);
        if (old == 31u) g_bar[TSTEPS * 8 + mi] = 0u;   // last passer resets final
        for (int tt = ni; tt < TSTEPS; tt += 16) g_bar[tt * 8 + mi] = 0u;
    }

    if (warp < 2) {
        int row = cta * 2 + warp;
        const float* h = g_hyf + (size_t)row * NHID;
        float acc[NOUT];
#pragma unroll
        for (int o = 0; o < NOUT; ++o) acc[o] = 0.f;
        for (int k = lane; k < NHID; k += 32) {
            float hv = __ldcg(h + k);
#pragma unroll
            for (int o = 0; o < NOUT; ++o) acc[o] += hv * Wout[k * NOUT + o];
        }
#pragma unroll
        for (int o = 0; o < NOUT; ++o) {
#pragma unroll
            for (int s = 16; s > 0; s >>= 1)
                acc[o] += __shfl_xor_sync(0xffffffffu, acc[o], s);
        }
        if (lane == 0) {
#pragma unroll
            for (int o = 0; o < NOUT; ++o) out[row * NOUT + o] = acc[o] + bout[o];
        }
    }
}

// ---------------- launch ----------------
extern "C" void kernel_launch(void* const* d_in, const int* in_sizes, int n_in,
                              void* d_out, int out_size) {
    (void)in_sizes; (void)n_in; (void)out_size;
    const float* x    = (const float*)d_in[0];
    const float* W    = (const float*)d_in[1];
    const float* b    = (const float*)d_in[2];
    const float* Wout = (const float*)d_in[3];
    const float* bout = (const float*)d_in[4];
    float* out = (float*)d_out;

    cornn_persist<<<NCTA, THREADS>>>(x, W, b, Wout, bout, out);
}